// round 17
// baseline (speedup 1.0000x reference)
#include <cuda_runtime.h>

// Problem constants (SUBDIVISIONS=7, BATCH=16)
#define BATCH 16
#define YDIM  640
#define XDIM  256
#define BH    128            // YDIM/5
#define YX    (YDIM*XDIM)    // 163840
#define NV    (YX + 2)       // 163842 vertices
#define BPT   4              // batches per k_loss launch (one batch group)
#define NGRP  (BATCH / BPT)  // 4 pipelined batch groups

// CSR over the sorted unique directed edge list (np.unique -> lexicographic):
// deg(v) = 5 for the 12 original icosahedron vertices (indices 0..11),
// 6 otherwise; offset(v) = prefix sum, closed form.
__device__ __forceinline__ int csr_off(int v) { return v < 12 ? 5 * v : 6 * v - 12; }
__device__ __forceinline__ int csr_deg(int v) { return v < 12 ? 5 : 6; }

// Scratch (static __device__ — no allocation allowed)
__device__ float4 g_v4[BATCH * NV];   // padded xyz_ per batch (~42 MB)
__device__ int    g_succ[NV * 6];     // ring-successor per directed edge slot
__device__ double g_acc;              // fused loss accumulator
__device__ unsigned int g_done;       // ticket counter for fused finalization

// ---------------------------------------------------------------------------
// K1: build v = [grid verts ; top pole ; bottom pole] as float4 (w unused).
// One launch per batch group (b0 = group*BPT), so each k_loss group can
// start as soon as ITS batches are built. inputs layout: (B, 3, Y, X).
// ---------------------------------------------------------------------------
__global__ void k_build_v(const float* __restrict__ inp, int b0) {
    int vtx = blockIdx.x * blockDim.x + threadIdx.x;
    int b   = b0 + blockIdx.y;
    if (vtx > YX + 1) return;
    const float* base = inp + (size_t)b * 3 * YX;
    float4 o;
    o.w = 0.0f;
    if (vtx < YX) {
        o.x = base[vtx];
        o.y = base[YX + vtx];
        o.z = base[2 * YX + vtx];
    } else if (vtx == YX) {
        float s[3];
        #pragma unroll
        for (int c = 0; c < 3; c++) {
            s[c] = 0.0f;
            #pragma unroll
            for (int i = 0; i < 5; i++) s[c] += base[c * YX + (i * BH) * XDIM];
            s[c] *= 0.2f;
        }
        o.x = s[0]; o.y = s[1]; o.z = s[2];
    } else {
        float s[3];
        #pragma unroll
        for (int c = 0; c < 3; c++) {
            s[c] = 0.0f;
            #pragma unroll
            for (int i = 1; i <= 5; i++)
                s[c] += base[c * YX + (i * BH - 1) * XDIM + (XDIM - 1)];
            s[c] *= 0.2f;
        }
        o.x = s[0]; o.y = s[1]; o.z = s[2];
    }
    g_v4[(size_t)b * NV + vtx] = o;
}

// ---------------------------------------------------------------------------
// K2: build the ring-successor map with NO atomics.
// Face (v,a,b) (oriented) defines succ(v->a) = b. The slot for directed edge
// v->a is a's position in v's sorted CSR segment of edge_dst — unique per
// directed edge, so each slot is written exactly once (no counters/memset).
// The 6-int segment [off, off+6), off = 6v-12, lies inside the two aligned
// 16B words at base = off & ~3 (off-base in {0,2}; worst-case read
// base+7 == E-1, in range): two LDG.128 + uniform selects. v<12 (60
// corners) takes a scalar path. Thread 0 resets accumulator + ticket.
// ---------------------------------------------------------------------------
__device__ __forceinline__ void store_succ(const int* __restrict__ edst,
                                           int v, int a, int b) {
    if (v >= 12) {
        int off  = 6 * v - 12;
        int base = off & ~3;
        const int4* P = (const int4*)(edst + base);
        int4 A = __ldg(P), B = __ldg(P + 1);
        int e1, e2, e3, e4, e5;
        if (off & 2) { e1 = A.w; e2 = B.x; e3 = B.y; e4 = B.z; e5 = B.w; }
        else         { e1 = A.y; e2 = A.z; e3 = A.w; e4 = B.x; e5 = B.y; }
        int pos = 0;
        if (e1 == a) pos = 1;
        if (e2 == a) pos = 2;
        if (e3 == a) pos = 3;
        if (e4 == a) pos = 4;
        if (e5 == a) pos = 5;
        g_succ[off + pos] = b;
    } else {
        int off = 5 * v;
        int pos = 0;
        #pragma unroll
        for (int i = 0; i < 5; i++)
            if (__ldg(edst + off + i) == a) pos = i;
        g_succ[off + pos] = b;
    }
}

__global__ void k_ring(const int* __restrict__ faces,
                       const int* __restrict__ edst, int F) {
    int f = blockIdx.x * blockDim.x + threadIdx.x;
    if (f == 0) { g_acc = 0.0; g_done = 0u; }
    if (f >= F) return;
    int a = faces[3 * f], b = faces[3 * f + 1], c = faces[3 * f + 2];
    store_succ(edst, a, b, c);
    store_succ(edst, b, c, a);
    store_succ(edst, c, a, b);
}

// ---------------------------------------------------------------------------
// K3: fused loss for one batch group (bgroup). One thread per vertex,
// BPT batches per thread. Neighbor list d[] from the sorted CSR edge_dst
// segment (coalesced); ring order walks g_succ; d[0] is the minimal
// neighbor so the coalescing rotation is free. deg-5: slot 5 duplicates
// n[0] so the wrap cross term vanishes. ||u|| == 1 by construction.
// nblocks counts blocks over ALL groups; last block writes the scalar.
// ---------------------------------------------------------------------------
__global__ void __launch_bounds__(128)
k_loss(const int* __restrict__ edst, const float* __restrict__ target,
       float* __restrict__ out, unsigned int nblocks, int bgroup) {
    int vtx = blockIdx.x * blockDim.x + threadIdx.x;
    float local = 0.0f;
    if (vtx < NV) {
        int off = csr_off(vtx);
        int cnt = csr_deg(vtx);
        int d[6], s[6];
        #pragma unroll
        for (int i = 0; i < 6; i++) {
            // off+5 <= E-1 even for the last vertex (off(NV-1)+6 == E)
            d[i] = edst[off + i];
            s[i] = g_succ[off + i];
        }
        // walk the ring: start at the minimal neighbor d[0]
        int n[6];
        n[0] = d[0];
        int nxt = s[0];
        #pragma unroll
        for (int k = 1; k < 6; k++) {
            n[k] = nxt;
            int nn_ = nxt;
            #pragma unroll
            for (int i = 0; i < 6; i++)
                if (i < cnt && d[i] == nxt) nn_ = s[i];
            nxt = nn_;
        }
        if (cnt == 5) n[5] = n[0];       // duplicated: wrap cross term = 0

        float invd = 1.0f / (float)cnt;
        const float inv3 = 1.0f / 3.0f;

        #pragma unroll
        for (int bb = 0; bb < BPT; bb++) {
            int b = bgroup * BPT + bb;
            const float4* vb = g_v4 + (size_t)b * NV;

            float4 p[6];
            #pragma unroll
            for (int i = 0; i < 6; i++) p[i] = __ldg(vb + n[i]);
            float4 pv = __ldg(vb + vtx);

            // ring-ordered cross sum: vn = sum_j p_j x p_{(j+1)%6}
            float nx = 0.f, ny = 0.f, nz = 0.f;
            #pragma unroll
            for (int j = 0; j < 6; j++) {
                const float4 a = p[j];
                const float4 c = p[(j + 1) % 6];
                nx += a.y * c.z - a.z * c.y;
                ny += a.z * c.x - a.x * c.z;
                nz += a.x * c.y - a.y * c.x;
            }
            // neighbor sum (subtract the duplicated n0 if deg==5)
            float sx = 0.f, sy = 0.f, sz = 0.f;
            #pragma unroll
            for (int j = 0; j < 6; j++) { sx += p[j].x; sy += p[j].y; sz += p[j].z; }
            if (cnt == 5) { sx -= p[0].x; sy -= p[0].y; sz -= p[0].z; }

            const float* t = target + (size_t)b * 9 * NV + vtx;
            // position loss (streamed target reads: evict-first)
            float dx = pv.x - __ldcs(t);
            float dy = pv.y - __ldcs(t + (size_t)NV);
            float dz = pv.z - __ldcs(t + 2 * (size_t)NV);
            float lpos = dx * dx + dy * dy + dz * dz;
            // normal cosine loss: ||u|| == 1 by construction
            float nn  = sqrtf(nx * nx + ny * ny + nz * nz);
            float inv = 1.0f / fmaxf(nn, 1e-12f);
            float ux = nx * inv, uy = ny * inv, uz = nz * inv;
            float tx = __ldcs(t + 3 * (size_t)NV);
            float ty = __ldcs(t + 4 * (size_t)NV);
            float tz = __ldcs(t + 5 * (size_t)NV);
            float tn = sqrtf(tx * tx + ty * ty + tz * tz);
            float cosv = (ux * tx + uy * ty + uz * tz) / fmaxf(tn, 1e-8f);
            // Laplacian loss
            float dlx = (pv.x - sx * invd) - __ldcs(t + 6 * (size_t)NV);
            float dly = (pv.y - sy * invd) - __ldcs(t + 7 * (size_t)NV);
            float dlz = (pv.z - sz * invd) - __ldcs(t + 8 * (size_t)NV);
            float llap = dlx * dlx + dly * dly + dlz * dlz;

            local += (lpos + llap) * inv3 + (1.0f - cosv);
        }
    }

    // warp shuffle reduce, then cross-warp smem reduce, one atomic per block
    #pragma unroll
    for (int off2 = 16; off2 > 0; off2 >>= 1)
        local += __shfl_xor_sync(0xFFFFFFFFu, local, off2);
    __shared__ float shw[4];
    int wid = threadIdx.x >> 5;
    if ((threadIdx.x & 31) == 0) shw[wid] = local;
    __syncthreads();
    if (threadIdx.x == 0) {
        float s = shw[0] + shw[1] + shw[2] + shw[3];
        atomicAdd(&g_acc, (double)s);
        __threadfence();
        unsigned int ticket = atomicAdd(&g_done, 1u);
        if (ticket == nblocks - 1u) {
            out[0] = (float)(g_acc / ((double)BATCH * (double)NV));
        }
    }
}

extern "C" void kernel_launch(void* const* d_in, const int* in_sizes, int n_in,
                              void* d_out, int out_size) {
    const float* inputs = (const float*)d_in[0];
    const float* target = (const float*)d_in[1];
    const int*   faces  = (const int*)  d_in[2];
    const int*   edst   = (const int*)  d_in[4];
    int F = in_sizes[2] / 3;

    // Pipelined fork-join: k_ring on the side stream; build_v split into
    // NGRP per-batch-group launches on main, each publishing an event; each
    // k_loss group launch (side stream) waits only on k_ring (stream order)
    // + its own build slice — so loss group 0 starts as soon as k_ring and
    // slice 0 are done, with the remaining build slices overlapping it.
    // One-time stream/event setup on the eager correctness call.
    static cudaStream_t s_side = nullptr;
    static cudaEvent_t  s_fork = nullptr, s_done = nullptr;
    static cudaEvent_t  e_b[NGRP] = {nullptr, nullptr, nullptr, nullptr};
    if (s_side == nullptr) {
        cudaStreamCreateWithFlags(&s_side, cudaStreamNonBlocking);
        cudaEventCreateWithFlags(&s_fork, cudaEventDisableTiming);
        cudaEventCreateWithFlags(&s_done, cudaEventDisableTiming);
        for (int g = 0; g < NGRP; g++)
            cudaEventCreateWithFlags(&e_b[g], cudaEventDisableTiming);
    }
    cudaStream_t main_s = 0;

    dim3 blk256(256);

    // fork
    cudaEventRecord(s_fork, main_s);
    cudaStreamWaitEvent(s_side, s_fork, 0);

    // side stream: build ring-successor map (no atomics)
    k_ring<<<(F + 255) / 256, blk256, 0, s_side>>>(faces, edst, F);

    // main stream: build vertex slices per batch group, publish events
    for (int g = 0; g < NGRP; g++) {
        k_build_v<<<dim3((YX + 2 + 255) / 256, BPT), blk256, 0, main_s>>>(
            inputs, g * BPT);
        cudaEventRecord(e_b[g], main_s);
    }

    // side stream: loss per group, gated on k_ring (stream order) + slice g
    dim3 lgrid((NV + 127) / 128, 1);
    unsigned int nblocks = lgrid.x * NGRP;
    for (int g = 0; g < NGRP; g++) {
        cudaStreamWaitEvent(s_side, e_b[g], 0);
        k_loss<<<lgrid, 128, 0, s_side>>>(edst, target, (float*)d_out,
                                          nblocks, g);
    }

    // rejoin main so the captured graph has a single sink
    cudaEventRecord(s_done, s_side);
    cudaStreamWaitEvent(main_s, s_done, 0);
}